// round 9
// baseline (speedup 1.0000x reference)
#include <cuda_runtime.h>
#include <cuda_bf16.h>
#include <cstdint>

#define DI __device__ __forceinline__

// bitsandbytes FP4 codebook (sign = bit 3)
__constant__ float FP4_TAB[16] = {
     0.0f,  0.0052083333f,  0.6666667f,  1.0f,  0.3333333f,  0.5f,  0.1666667f,  0.25f,
    -0.0f, -0.0052083333f, -0.6666667f, -1.0f, -0.3333333f, -0.5f, -0.1666667f, -0.25f};

#define B_ 16384L
#define I_ 2048L
#define H_ 4096L
#define O_ 2048L

// scratch (alloc-free rule: __device__ globals). All values are exact bf16
// values stored in f32 (the reference computes on bf16 tensors upcast to f32).
__device__ float g_Xf[B_ * I_];
__device__ float g_W1f[H_ * I_];
__device__ float g_W2f[H_ * H_];
__device__ float g_W3f[O_ * H_];
__device__ float g_H1f[B_ * H_];
__device__ float g_H2f[B_ * H_];

DI float bf16v(float x) { return __bfloat162float(__float2bfloat16(x)); }

// packed dual-FP32 FMA (Blackwell FFMA2). Per-lane IEEE RN fma — bit-identical
// to two scalar fmaf calls, so accumulation-order semantics are unchanged.
DI void fma2(uint64_t& d, uint64_t a, uint64_t b) {
    asm("fma.rn.f32x2 %0, %1, %2, %3;" : "=l"(d) : "l"(a), "l"(b), "l"(d));
}
DI void unpack2(float& lo, float& hi, uint64_t v) {
    asm("mov.b64 {%0, %1}, %2;" : "=f"(lo), "=f"(hi) : "l"(v));
}

// ---------------------------------------------------------------------------
// Elementwise prep: produce f32 tensors holding exact bf16 values
// ---------------------------------------------------------------------------

__global__ void cast_kernel(const float* __restrict__ x, float* __restrict__ y) {
    long i4 = blockIdx.x * (long)blockDim.x + threadIdx.x;
    float4 v = reinterpret_cast<const float4*>(x)[i4];
    float4 o;
    o.x = bf16v(v.x); o.y = bf16v(v.y); o.z = bf16v(v.z); o.w = bf16v(v.w);
    reinterpret_cast<float4*>(y)[i4] = o;
}

__global__ void dequant_kernel(const int* __restrict__ codes,
                               const float* __restrict__ absmax,
                               float* __restrict__ w) {
    long i4 = blockIdx.x * (long)blockDim.x + threadIdx.x;  // 4 elements per thread
    int4 c = reinterpret_cast<const int4*>(codes)[i4];
    float am = __ldg(&absmax[(i4 * 4) >> 6]);  // 4 consecutive elems share a 64-block
    float4 o;
    o.x = bf16v(FP4_TAB[c.x & 15] * am);
    o.y = bf16v(FP4_TAB[c.y & 15] * am);
    o.z = bf16v(FP4_TAB[c.z & 15] * am);
    o.w = bf16v(FP4_TAB[c.w & 15] * am);
    reinterpret_cast<float4*>(w)[i4] = o;
}

// ---------------------------------------------------------------------------
// Order-exact SGEMM on the FFMA2 (f32x2) pipe, A duplicated in smem so the
// mainloop has ZERO register-packing MOVs: 32 FFMA2 + 6 LDS.128 per warp-k.
// C[M,N] = relu?( bf16( bf16(seq_fma_acc) + bf16(bias) ) )
// Each output element remains ONE sequential IEEE-FMA chain over k ascending
// (bit-identical to R7/R8, which passed at 5.398e-4).
// BM=BN=128, BK=16, 256 threads / 8 warps (2m x 4n), warp tile 64x32,
// lane grid 8x4, 8x8 outputs/thread (4 j-pairs), double-buffered smem.
// ---------------------------------------------------------------------------

constexpr int BK = 16;
constexpr int LWA = 264;   // A-dup row: 256 floats + pad (div 4 for LDS.128)
constexpr int LWB = 132;   // B row: 128 floats + pad

template <bool RELU>
__global__ void __launch_bounds__(256, 2)
sgemm_f32x2(const float* __restrict__ A,   // [M,K] f32 (bf16 values)
            const float* __restrict__ W,   // [N,K] f32 (bf16 values)
            const float* __restrict__ bias,
            float* __restrict__ C,         // [M,N] f32 (bf16 values)
            int M, int N, int K) {
    constexpr int BM = 128, BN = 128;
    __shared__ __align__(16) float sA[2][BK][LWA];  // duplicated: [k][2m],[k][2m+1]
    __shared__ __align__(16) float sB[2][BK][LWB];

    const int tid  = threadIdx.x;
    const int lane = tid & 31;
    const int warp = tid >> 5;
    const int wm = (warp & 1) * 64;     // warp m offset
    const int wn = (warp >> 1) * 32;    // warp n offset
    const int lr = lane >> 2;           // 0..7  -> row group (8 rows)
    const int lc = lane & 3;            // 0..3  -> col group (8 cols)
    const int m0 = blockIdx.y * BM;
    const int n0 = blockIdx.x * BN;

    // gmem->smem staging: each thread owns one tile-row half (8 floats)
    const int sr = tid >> 1;            // 0..127
    const int sc = (tid & 1) * 8;       // 0 or 8

    const float* gA = A + (size_t)(m0 + sr) * K + sc;
    const float* gW = W + (size_t)(n0 + sr) * K + sc;

    uint64_t acc[8][4];
#pragma unroll
    for (int i = 0; i < 8; i++)
#pragma unroll
        for (int j = 0; j < 4; j++) acc[i][j] = 0ull;

    float ra[8], rb[8];
    auto gload = [&]() {
        *reinterpret_cast<float4*>(ra)     = *reinterpret_cast<const float4*>(gA);
        *reinterpret_cast<float4*>(ra + 4) = *reinterpret_cast<const float4*>(gA + 4);
        *reinterpret_cast<float4*>(rb)     = *reinterpret_cast<const float4*>(gW);
        *reinterpret_cast<float4*>(rb + 4) = *reinterpret_cast<const float4*>(gW + 4);
    };
    auto sstore = [&](int st) {
#pragma unroll
        for (int t = 0; t < 8; t++) {
            sA[st][sc + t][2 * sr]     = ra[t];   // duplicate A
            sA[st][sc + t][2 * sr + 1] = ra[t];
            sB[st][sc + t][sr]         = rb[t];
        }
    };

    const int KT = K / BK;
    gload();
    sstore(0);
    __syncthreads();

    for (int kt = 0; kt < KT; ++kt) {
        const int s = kt & 1;
        if (kt + 1 < KT) { gA += BK; gW += BK; gload(); }

#pragma unroll
        for (int k = 0; k < BK; k++) {   // ascending k — preserves chain order
            uint64_t ad[4], bp[4];
            const uint64_t* aq = reinterpret_cast<const uint64_t*>(&sA[s][k][2 * (wm + lr * 8)]);
            const uint64_t* bq = reinterpret_cast<const uint64_t*>(&sB[s][k][wn + lc * 8]);
            ad[0] = aq[0]; ad[1] = aq[1]; ad[2] = aq[2]; ad[3] = aq[3];
            bp[0] = bq[0]; bp[1] = bq[1]; bp[2] = bq[2]; bp[3] = bq[3];
#pragma unroll
            for (int ih = 0; ih < 4; ih++) {
                float a0, a1;
                unpack2(a0, a1, ad[ih]);   // two adjacent duplicated a values
                const uint64_t d0 = ad[ih];
                // d0 = (a[2ih], a[2ih]) requires re-pairing: ad[ih] holds
                // (a[2ih] dup) already — each uint64 IS one duplicated value.
#pragma unroll
                for (int j = 0; j < 4; j++)
                    fma2(acc[2 * ih][j], d0, bp[j]);
            }
            // second set: rows 2ih+1 come from the odd uint64s
            const uint64_t* aq2 = aq + 4;
            uint64_t ad2[4];
            ad2[0] = aq2[0]; ad2[1] = aq2[1]; ad2[2] = aq2[2]; ad2[3] = aq2[3];
#pragma unroll
            for (int ih = 0; ih < 4; ih++) {
#pragma unroll
                for (int j = 0; j < 4; j++)
                    fma2(acc[2 * ih + 1][j], ad2[ih], bp[j]);
            }
        }

        if (kt + 1 < KT) sstore(s ^ 1);
        __syncthreads();
    }

    // NOTE on a-row mapping: sA dup row holds a-values at uint64 index m
    // (pair (2m,2m+1) bytes) — uint64 q of the 8-row group corresponds to
    // a-row (wm + lr*8 + q). Loads above: aq[0..3] -> rows +0..3,
    // aq2[0..3] -> rows +4..7. acc rows must match that order:
    // acc[2*ih][..] used rows 0..3 and acc[2*ih+1][..] rows 4..7 — so the
    // accumulator row index mapping is: phys row r = (r<4 ? 2*r : 2*(r-4)+1).
    // We undo this permutation in the epilogue below.

    float bb[8];
#pragma unroll
    for (int j = 0; j < 8; j++) bb[j] = bf16v(bias[n0 + wn + lc * 8 + j]);

#pragma unroll
    for (int q = 0; q < 8; q++) {
        // accumulator slot -> physical row: slots 0,2,4,6 = rows 0..3 ; slots 1,3,5,7 = rows 4..7
        const int slot = (q < 4) ? (2 * q) : (2 * (q - 4) + 1);
        const int row = m0 + wm + lr * 8 + q;
        float out[8];
#pragma unroll
        for (int j = 0; j < 4; j++) {
            float v0, v1;
            unpack2(v0, v1, acc[slot][j]);
            v0 = bf16v(bf16v(v0) + bb[2 * j]);
            v1 = bf16v(bf16v(v1) + bb[2 * j + 1]);
            if (RELU) { v0 = fmaxf(v0, 0.f); v1 = fmaxf(v1, 0.f); }
            out[2 * j] = v0; out[2 * j + 1] = v1;
        }
        float* cp = &C[(size_t)row * N + n0 + wn + lc * 8];
        *reinterpret_cast<float4*>(cp)     = *reinterpret_cast<float4*>(out);
        *reinterpret_cast<float4*>(cp + 4) = *reinterpret_cast<float4*>(out + 4);
    }
}

// ---------------------------------------------------------------------------

extern "C" void kernel_launch(void* const* d_in, const int* in_sizes, int n_in,
                              void* d_out, int out_size) {
    // Resolve inputs by element count (robust to metadata ordering).
    const float* x = nullptr;
    const int *codes1 = nullptr, *codes2 = nullptr, *codes3 = nullptr;
    const float *absmax1 = nullptr, *absmax2 = nullptr, *absmax3 = nullptr;
    const float *bias1 = nullptr, *bias2 = nullptr, *bias3 = nullptr;

    for (int i = 0; i < n_in; i++) {
        const long sz = in_sizes[i];
        const void* p = d_in[i];
        if (sz == B_ * I_) x = (const float*)p;
        else if (sz == H_ * H_) codes2 = (const int*)p;
        else if (sz == H_ * I_) { if (!codes1) codes1 = (const int*)p; else codes3 = (const int*)p; }
        else if (sz == (H_ * H_) / 64) absmax2 = (const float*)p;
        else if (sz == (H_ * I_) / 64) { if (!absmax1) absmax1 = (const float*)p; else absmax3 = (const float*)p; }
        else if (sz == H_) { if (!bias1) bias1 = (const float*)p; else bias2 = (const float*)p; }
        else if (sz == O_) bias3 = (const float*)p;
    }

    float *Xf, *W1, *W2, *W3, *H1, *H2;
    cudaGetSymbolAddress((void**)&Xf, g_Xf);
    cudaGetSymbolAddress((void**)&W1, g_W1f);
    cudaGetSymbolAddress((void**)&W2, g_W2f);
    cudaGetSymbolAddress((void**)&W3, g_W3f);
    cudaGetSymbolAddress((void**)&H1, g_H1f);
    cudaGetSymbolAddress((void**)&H2, g_H2f);

    // elementwise prep
    cast_kernel<<<(unsigned)((B_ * I_) / 4 / 256), 256>>>(x, Xf);
    dequant_kernel<<<(unsigned)((H_ * I_) / 4 / 256), 256>>>(codes1, absmax1, W1);
    dequant_kernel<<<(unsigned)((H_ * H_) / 4 / 256), 256>>>(codes2, absmax2, W2);
    dequant_kernel<<<(unsigned)((O_ * H_) / 4 / 256), 256>>>(codes3, absmax3, W3);

    // layer 1: [16384,2048] @ [4096,2048]^T -> relu -> H1
    sgemm_f32x2<true><<<dim3(H_ / 128, B_ / 128), 256>>>(
        Xf, W1, bias1, H1, (int)B_, (int)H_, (int)I_);
    // layer 2: [16384,4096] @ [4096,4096]^T -> relu -> H2
    sgemm_f32x2<true><<<dim3(H_ / 128, B_ / 128), 256>>>(
        H1, W2, bias2, H2, (int)B_, (int)H_, (int)H_);
    // layer 3: [16384,4096] @ [2048,4096]^T -> d_out (f32 = upcast bf16)
    sgemm_f32x2<false><<<dim3(O_ / 128, B_ / 128), 256>>>(
        H2, W3, bias3, (float*)d_out, (int)B_, (int)O_, (int)H_);
}

// round 10
// speedup vs baseline: 1.5947x; 1.5947x over previous
#include <cuda_runtime.h>
#include <cuda_bf16.h>
#include <cstdint>

#define DI __device__ __forceinline__

// bitsandbytes FP4 codebook (sign = bit 3)
__constant__ float FP4_TAB[16] = {
     0.0f,  0.0052083333f,  0.6666667f,  1.0f,  0.3333333f,  0.5f,  0.1666667f,  0.25f,
    -0.0f, -0.0052083333f, -0.6666667f, -1.0f, -0.3333333f, -0.5f, -0.1666667f, -0.25f};

#define B_ 16384L
#define I_ 2048L
#define H_ 4096L
#define O_ 2048L

// scratch (alloc-free rule: __device__ globals)
__device__ float g_Xf[B_ * I_];           // exact bf16 values in f32
__device__ float g_W1f[H_ * I_];
__device__ float g_W2f[H_ * H_];
__device__ float g_H1f[B_ * H_];
__device__ __nv_bfloat16 g_H2b[B_ * H_];  // layer-2 output, bf16 (exact)
__device__ __nv_bfloat16 g_W3b[O_ * H_];  // layer-3 weights, bf16

DI float bf16v(float x) { return __bfloat162float(__float2bfloat16(x)); }

// packed dual-FP32 FMA (Blackwell FFMA2). Per-lane IEEE RN fma — bit-identical
// to two scalar fmaf calls, so accumulation-order semantics are unchanged.
DI void fma2(uint64_t& d, uint64_t a, uint64_t b) {
    asm("fma.rn.f32x2 %0, %1, %2, %3;" : "=l"(d) : "l"(a), "l"(b), "l"(d));
}
DI uint64_t pack2(float lo, float hi) {
    uint64_t r;
    asm("mov.b64 %0, {%1, %2};" : "=l"(r) : "f"(lo), "f"(hi));
    return r;
}
DI void unpack2(float& lo, float& hi, uint64_t v) {
    asm("mov.b64 {%0, %1}, %2;" : "=f"(lo), "=f"(hi) : "l"(v));
}

DI uint32_t s2u(const void* p) { return (uint32_t)__cvta_generic_to_shared(p); }
DI void cp16(uint32_t s, const void* g) {
    asm volatile("cp.async.cg.shared.global [%0], [%1], 16;\n" :: "r"(s), "l"(g) : "memory");
}
DI void cp_commit() { asm volatile("cp.async.commit_group;\n" ::: "memory"); }
template <int N>
DI void cp_wait() { asm volatile("cp.async.wait_group %0;\n" :: "n"(N) : "memory"); }
DI uint32_t lds32u(const __nv_bfloat16* p) { return *reinterpret_cast<const uint32_t*>(p); }
DI void mma16816(float* c, const uint32_t* a, const uint32_t* b) {
    asm volatile(
        "mma.sync.aligned.m16n8k16.row.col.f32.bf16.bf16.f32 "
        "{%0,%1,%2,%3}, {%4,%5,%6,%7}, {%8,%9}, {%0,%1,%2,%3};\n"
        : "+f"(c[0]), "+f"(c[1]), "+f"(c[2]), "+f"(c[3])
        : "r"(a[0]), "r"(a[1]), "r"(a[2]), "r"(a[3]), "r"(b[0]), "r"(b[1]));
}

// ---------------------------------------------------------------------------
// Elementwise prep
// ---------------------------------------------------------------------------

__global__ void cast_kernel(const float* __restrict__ x, float* __restrict__ y) {
    long i4 = blockIdx.x * (long)blockDim.x + threadIdx.x;
    float4 v = reinterpret_cast<const float4*>(x)[i4];
    float4 o;
    o.x = bf16v(v.x); o.y = bf16v(v.y); o.z = bf16v(v.z); o.w = bf16v(v.w);
    reinterpret_cast<float4*>(y)[i4] = o;
}

__global__ void dequant_kernel_f32(const int* __restrict__ codes,
                                   const float* __restrict__ absmax,
                                   float* __restrict__ w) {
    long i4 = blockIdx.x * (long)blockDim.x + threadIdx.x;
    int4 c = reinterpret_cast<const int4*>(codes)[i4];
    float am = __ldg(&absmax[(i4 * 4) >> 6]);
    float4 o;
    o.x = bf16v(FP4_TAB[c.x & 15] * am);
    o.y = bf16v(FP4_TAB[c.y & 15] * am);
    o.z = bf16v(FP4_TAB[c.z & 15] * am);
    o.w = bf16v(FP4_TAB[c.w & 15] * am);
    reinterpret_cast<float4*>(w)[i4] = o;
}

__global__ void dequant_kernel_bf16(const int* __restrict__ codes,
                                    const float* __restrict__ absmax,
                                    __nv_bfloat16* __restrict__ w) {
    long i4 = blockIdx.x * (long)blockDim.x + threadIdx.x;
    int4 c = reinterpret_cast<const int4*>(codes)[i4];
    float am = __ldg(&absmax[(i4 * 4) >> 6]);
    __nv_bfloat162 p0 = __floats2bfloat162_rn(FP4_TAB[c.x & 15] * am, FP4_TAB[c.y & 15] * am);
    __nv_bfloat162 p1 = __floats2bfloat162_rn(FP4_TAB[c.z & 15] * am, FP4_TAB[c.w & 15] * am);
    reinterpret_cast<__nv_bfloat162*>(w)[i4 * 2 + 0] = p0;
    reinterpret_cast<__nv_bfloat162*>(w)[i4 * 2 + 1] = p1;
}

// ---------------------------------------------------------------------------
// Layers 1-2: order-exact SGEMM on the FFMA2 pipe (R8 kernel, verbatim core).
// Each output element is ONE sequential IEEE-FMA chain over ascending k.
// OUTB: write bf16 (exact conversion) instead of f32.
// ---------------------------------------------------------------------------

template <bool OUTB>
__global__ void __launch_bounds__(256)
sgemm_f32x2(const float* __restrict__ A,   // [M,K] f32 (bf16 values)
            const float* __restrict__ W,   // [N,K] f32 (bf16 values)
            const float* __restrict__ bias,
            void* __restrict__ Cv,         // f32 or bf16
            int M, int N, int K) {
    constexpr int BM = 128, BN = 128, BK = 16, LW = 132;
    __shared__ __align__(16) float sA[BK][LW];
    __shared__ __align__(16) float sB[BK][LW];

    const int tid  = threadIdx.x;
    const int lane = tid & 31;
    const int warp = tid >> 5;
    const int wm = (warp & 1) * 64;
    const int wn = (warp >> 1) * 32;
    const int lr = lane >> 2;
    const int lc = lane & 3;
    const int m0 = blockIdx.y * BM;
    const int n0 = blockIdx.x * BN;

    const int sr = tid >> 1;
    const int sc = (tid & 1) * 8;

    const float* gA = A + (size_t)(m0 + sr) * K + sc;
    const float* gW = W + (size_t)(n0 + sr) * K + sc;

    uint64_t acc[8][4];
    const uint64_t z2 = pack2(0.f, 0.f);
#pragma unroll
    for (int i = 0; i < 8; i++)
#pragma unroll
        for (int j = 0; j < 4; j++) acc[i][j] = z2;

    float4 ra0 = *reinterpret_cast<const float4*>(gA);
    float4 ra1 = *reinterpret_cast<const float4*>(gA + 4);
    float4 rb0 = *reinterpret_cast<const float4*>(gW);
    float4 rb1 = *reinterpret_cast<const float4*>(gW + 4);

    const int KT = K / BK;
    for (int kt = 0; kt < KT; ++kt) {
        sA[sc + 0][sr] = ra0.x; sA[sc + 1][sr] = ra0.y;
        sA[sc + 2][sr] = ra0.z; sA[sc + 3][sr] = ra0.w;
        sA[sc + 4][sr] = ra1.x; sA[sc + 5][sr] = ra1.y;
        sA[sc + 6][sr] = ra1.z; sA[sc + 7][sr] = ra1.w;
        sB[sc + 0][sr] = rb0.x; sB[sc + 1][sr] = rb0.y;
        sB[sc + 2][sr] = rb0.z; sB[sc + 3][sr] = rb0.w;
        sB[sc + 4][sr] = rb1.x; sB[sc + 5][sr] = rb1.y;
        sB[sc + 6][sr] = rb1.z; sB[sc + 7][sr] = rb1.w;
        __syncthreads();

        if (kt + 1 < KT) {
            gA += BK; gW += BK;
            ra0 = *reinterpret_cast<const float4*>(gA);
            ra1 = *reinterpret_cast<const float4*>(gA + 4);
            rb0 = *reinterpret_cast<const float4*>(gW);
            rb1 = *reinterpret_cast<const float4*>(gW + 4);
        }

#pragma unroll
        for (int k = 0; k < BK; k++) {   // ascending k — preserves chain order
            float a[8];
            *reinterpret_cast<float4*>(a)     = *reinterpret_cast<const float4*>(&sA[k][wm + lr * 8]);
            *reinterpret_cast<float4*>(a + 4) = *reinterpret_cast<const float4*>(&sA[k][wm + lr * 8 + 4]);
            uint64_t bp[4];
            const uint64_t* bq = reinterpret_cast<const uint64_t*>(&sB[k][wn + lc * 8]);
            bp[0] = bq[0]; bp[1] = bq[1]; bp[2] = bq[2]; bp[3] = bq[3];
#pragma unroll
            for (int i = 0; i < 8; i++) {
                const uint64_t ad = pack2(a[i], a[i]);
#pragma unroll
                for (int j = 0; j < 4; j++)
                    fma2(acc[i][j], ad, bp[j]);
            }
        }
        __syncthreads();
    }

    // Epilogue — reference rounding: bf16(matmul), + bf16(bias), bf16 round, relu.
    float bb[8];
#pragma unroll
    for (int j = 0; j < 8; j++) bb[j] = bf16v(bias[n0 + wn + lc * 8 + j]);

#pragma unroll
    for (int i = 0; i < 8; i++) {
        const int row = m0 + wm + lr * 8 + i;
        float out[8];
#pragma unroll
        for (int j = 0; j < 4; j++) {
            float v0, v1;
            unpack2(v0, v1, acc[i][j]);
            v0 = bf16v(bf16v(v0) + bb[2 * j]);
            v1 = bf16v(bf16v(v1) + bb[2 * j + 1]);
            v0 = fmaxf(v0, 0.f); v1 = fmaxf(v1, 0.f);   // layers 1-2 always relu
            out[2 * j] = v0; out[2 * j + 1] = v1;
        }
        if (OUTB) {
            __nv_bfloat16* cp = (__nv_bfloat16*)Cv + (size_t)row * N + n0 + wn + lc * 8;
            __nv_bfloat162 q0 = __floats2bfloat162_rn(out[0], out[1]);
            __nv_bfloat162 q1 = __floats2bfloat162_rn(out[2], out[3]);
            __nv_bfloat162 q2 = __floats2bfloat162_rn(out[4], out[5]);
            __nv_bfloat162 q3 = __floats2bfloat162_rn(out[6], out[7]);
            reinterpret_cast<__nv_bfloat162*>(cp)[0] = q0;
            reinterpret_cast<__nv_bfloat162*>(cp)[1] = q1;
            reinterpret_cast<__nv_bfloat162*>(cp)[2] = q2;
            reinterpret_cast<__nv_bfloat162*>(cp)[3] = q3;
        } else {
            float* cp = (float*)Cv + (size_t)row * N + n0 + wn + lc * 8;
            *reinterpret_cast<float4*>(cp)     = *reinterpret_cast<float4*>(out);
            *reinterpret_cast<float4*>(cp + 4) = *reinterpret_cast<float4*>(out + 4);
        }
    }
}

// ---------------------------------------------------------------------------
// Layer 3: HMMA bf16 GEMM (R4 kernel, proven-correct math; order noise at the
// LAST layer contributes only ~1e-4 — admissible). f32 output = upcast bf16.
// ---------------------------------------------------------------------------

__global__ void __launch_bounds__(256)
gemm_hmma_l3(const __nv_bfloat16* __restrict__ A,
             const __nv_bfloat16* __restrict__ W,
             const float* __restrict__ bias,
             float* __restrict__ C,
             int M, int N, int K) {
    constexpr int BM = 128, BN = 128, BK = 32;
    constexpr int LDS = BK + 8;

    __shared__ __align__(16) __nv_bfloat16 sA[2][BM * LDS];
    __shared__ __align__(16) __nv_bfloat16 sB[2][BN * LDS];

    const int tid = threadIdx.x;
    const int lane = tid & 31;
    const int warp = tid >> 5;
    const int wm = (warp & 1) * 64;
    const int wn = (warp >> 1) * 32;
    const int m0 = blockIdx.y * BM;
    const int n0 = blockIdx.x * BN;

    const int gid = lane >> 2;
    const int tg  = lane & 3;
    const int kfr = tg * 2;

    const int r_ld = tid >> 2;
    const int c_ld = (tid & 3) * 8;

    float acc[4][4][4];
#pragma unroll
    for (int i = 0; i < 4; i++)
#pragma unroll
        for (int j = 0; j < 4; j++)
#pragma unroll
            for (int q = 0; q < 4; q++) acc[i][j][q] = 0.f;

    auto load_stage = [&](int s, int kt) {
        const int k0 = kt * BK;
        const __nv_bfloat16* gA = A + (size_t)(m0 + r_ld) * K + k0 + c_ld;
        const __nv_bfloat16* gB = W + (size_t)(n0 + r_ld) * K + k0 + c_ld;
        cp16(s2u(&sA[s][r_ld * LDS + c_ld]), gA);
        cp16(s2u(&sB[s][r_ld * LDS + c_ld]), gB);
        cp16(s2u(&sA[s][(r_ld + 64) * LDS + c_ld]), gA + (size_t)64 * K);
        cp16(s2u(&sB[s][(r_ld + 64) * LDS + c_ld]), gB + (size_t)64 * K);
        cp_commit();
    };

    auto compute_stage = [&](int s) {
        const __nv_bfloat16* pA = sA[s];
        const __nv_bfloat16* pB = sB[s];
#pragma unroll
        for (int ks = 0; ks < 2; ks++) {
            const int kk = ks * 16;
            uint32_t a[4][4], b[4][2];
#pragma unroll
            for (int mt = 0; mt < 4; mt++) {
                const int r = wm + mt * 16 + gid;
                a[mt][0] = lds32u(&pA[(r    ) * LDS + kk + kfr    ]);
                a[mt][1] = lds32u(&pA[(r + 8) * LDS + kk + kfr    ]);
                a[mt][2] = lds32u(&pA[(r    ) * LDS + kk + kfr + 8]);
                a[mt][3] = lds32u(&pA[(r + 8) * LDS + kk + kfr + 8]);
            }
#pragma unroll
            for (int nt = 0; nt < 4; nt++) {
                const int n = wn + nt * 8 + gid;
                b[nt][0] = lds32u(&pB[n * LDS + kk + kfr    ]);
                b[nt][1] = lds32u(&pB[n * LDS + kk + kfr + 8]);
            }
#pragma unroll
            for (int mt = 0; mt < 4; mt++)
#pragma unroll
                for (int nt = 0; nt < 4; nt++)
                    mma16816(acc[mt][nt], a[mt], b[nt]);
        }
    };

    const int KT = K / BK;
    load_stage(0, 0);
    for (int kt = 0; kt < KT; ++kt) {
        if (kt + 1 < KT) {
            load_stage((kt + 1) & 1, kt + 1);
            cp_wait<1>();
        } else {
            cp_wait<0>();
        }
        __syncthreads();
        compute_stage(kt & 1);
        __syncthreads();
    }

    // Epilogue — reference rounding: bf16(dot) + bf16(bias) -> bf16, upcast f32.
#pragma unroll
    for (int mt = 0; mt < 4; mt++) {
        const int rr = m0 + wm + mt * 16 + gid;
#pragma unroll
        for (int nt = 0; nt < 4; nt++) {
            const int cc = n0 + wn + nt * 8 + tg * 2;
            const float b0 = bf16v(bias[cc]);
            const float b1 = bf16v(bias[cc + 1]);
            const float* cr = acc[mt][nt];

            float v0 = bf16v(bf16v(cr[0]) + b0);
            float v1 = bf16v(bf16v(cr[1]) + b1);
            float v2 = bf16v(bf16v(cr[2]) + b0);
            float v3 = bf16v(bf16v(cr[3]) + b1);
            *reinterpret_cast<float2*>(&C[(size_t)rr * N + cc]) = make_float2(v0, v1);
            *reinterpret_cast<float2*>(&C[(size_t)(rr + 8) * N + cc]) = make_float2(v2, v3);
        }
    }
}

// ---------------------------------------------------------------------------

extern "C" void kernel_launch(void* const* d_in, const int* in_sizes, int n_in,
                              void* d_out, int out_size) {
    // Resolve inputs by element count (robust to metadata ordering).
    const float* x = nullptr;
    const int *codes1 = nullptr, *codes2 = nullptr, *codes3 = nullptr;
    const float *absmax1 = nullptr, *absmax2 = nullptr, *absmax3 = nullptr;
    const float *bias1 = nullptr, *bias2 = nullptr, *bias3 = nullptr;

    for (int i = 0; i < n_in; i++) {
        const long sz = in_sizes[i];
        const void* p = d_in[i];
        if (sz == B_ * I_) x = (const float*)p;
        else if (sz == H_ * H_) codes2 = (const int*)p;
        else if (sz == H_ * I_) { if (!codes1) codes1 = (const int*)p; else codes3 = (const int*)p; }
        else if (sz == (H_ * H_) / 64) absmax2 = (const float*)p;
        else if (sz == (H_ * I_) / 64) { if (!absmax1) absmax1 = (const float*)p; else absmax3 = (const float*)p; }
        else if (sz == H_) { if (!bias1) bias1 = (const float*)p; else bias2 = (const float*)p; }
        else if (sz == O_) bias3 = (const float*)p;
    }

    float *Xf, *W1, *W2, *H1;
    __nv_bfloat16 *H2b, *W3b;
    cudaGetSymbolAddress((void**)&Xf, g_Xf);
    cudaGetSymbolAddress((void**)&W1, g_W1f);
    cudaGetSymbolAddress((void**)&W2, g_W2f);
    cudaGetSymbolAddress((void**)&H1, g_H1f);
    cudaGetSymbolAddress((void**)&H2b, g_H2b);
    cudaGetSymbolAddress((void**)&W3b, g_W3b);

    // elementwise prep
    cast_kernel<<<(unsigned)((B_ * I_) / 4 / 256), 256>>>(x, Xf);
    dequant_kernel_f32<<<(unsigned)((H_ * I_) / 4 / 256), 256>>>(codes1, absmax1, W1);
    dequant_kernel_f32<<<(unsigned)((H_ * H_) / 4 / 256), 256>>>(codes2, absmax2, W2);
    dequant_kernel_bf16<<<(unsigned)((O_ * H_) / 4 / 256), 256>>>(codes3, absmax3, W3b);

    // layer 1: sequential-chain f32x2, f32 out
    sgemm_f32x2<false><<<dim3(H_ / 128, B_ / 128), 256>>>(
        Xf, W1, bias1, H1, (int)B_, (int)H_, (int)I_);
    // layer 2: sequential-chain f32x2, bf16 out (exact conversion)
    sgemm_f32x2<true><<<dim3(H_ / 128, B_ / 128), 256>>>(
        H1, W2, bias2, H2b, (int)B_, (int)H_, (int)H_);
    // layer 3: HMMA bf16 (last-layer order noise ~1e-4 — admissible), f32 out
    gemm_hmma_l3<<<dim3(O_ / 128, B_ / 128), 256>>>(
        H2b, W3b, bias3, (float*)d_out, (int)B_, (int)O_, (int)H_);
}

// round 11
// speedup vs baseline: 3.2925x; 2.0647x over previous
#include <cuda_runtime.h>
#include <cuda_bf16.h>
#include <cstdint>

#define DI __device__ __forceinline__

// bitsandbytes FP4 codebook (sign = bit 3)
__constant__ float FP4_TAB[16] = {
     0.0f,  0.0052083333f,  0.6666667f,  1.0f,  0.3333333f,  0.5f,  0.1666667f,  0.25f,
    -0.0f, -0.0052083333f, -0.6666667f, -1.0f, -0.3333333f, -0.5f, -0.1666667f, -0.25f};

#define B_ 16384L
#define I_ 2048L
#define H_ 4096L
#define O_ 2048L

// scratch (alloc-free rule: __device__ globals)
__device__ float g_Xf[B_ * I_];           // exact bf16 values in f32 (layer-1 inputs)
__device__ float g_W1f[H_ * I_];
__device__ __nv_bfloat16 g_H1b[B_ * H_];  // layer-1 output, bf16 (exact)
__device__ __nv_bfloat16 g_W2b[H_ * H_];  // layer-2 weights, bf16
__device__ __nv_bfloat16 g_H2b[B_ * H_];  // layer-2 output, bf16
__device__ __nv_bfloat16 g_W3b[O_ * H_];  // layer-3 weights, bf16

DI float bf16v(float x) { return __bfloat162float(__float2bfloat16(x)); }

// packed dual-FP32 FMA (Blackwell FFMA2): per-lane IEEE RN fma.
DI void fma2(uint64_t& d, uint64_t a, uint64_t b) {
    asm("fma.rn.f32x2 %0, %1, %2, %3;" : "=l"(d) : "l"(a), "l"(b), "l"(d));
}
DI uint64_t pack2(float lo, float hi) {
    uint64_t r;
    asm("mov.b64 %0, {%1, %2};" : "=l"(r) : "f"(lo), "f"(hi));
    return r;
}
DI void unpack2(float& lo, float& hi, uint64_t v) {
    asm("mov.b64 {%0, %1}, %2;" : "=f"(lo), "=f"(hi) : "l"(v));
}

DI uint32_t s2u(const void* p) { return (uint32_t)__cvta_generic_to_shared(p); }
DI void cp16(uint32_t s, const void* g) {
    asm volatile("cp.async.cg.shared.global [%0], [%1], 16;\n" :: "r"(s), "l"(g) : "memory");
}
DI void cp_commit() { asm volatile("cp.async.commit_group;\n" ::: "memory"); }
template <int N>
DI void cp_wait() { asm volatile("cp.async.wait_group %0;\n" :: "n"(N) : "memory"); }
DI uint32_t lds32u(const __nv_bfloat16* p) { return *reinterpret_cast<const uint32_t*>(p); }
DI void mma16816(float* c, const uint32_t* a, const uint32_t* b) {
    asm volatile(
        "mma.sync.aligned.m16n8k16.row.col.f32.bf16.bf16.f32 "
        "{%0,%1,%2,%3}, {%4,%5,%6,%7}, {%8,%9}, {%0,%1,%2,%3};\n"
        : "+f"(c[0]), "+f"(c[1]), "+f"(c[2]), "+f"(c[3])
        : "r"(a[0]), "r"(a[1]), "r"(a[2]), "r"(a[3]), "r"(b[0]), "r"(b[1]));
}

// ---------------------------------------------------------------------------
// Elementwise prep
// ---------------------------------------------------------------------------

__global__ void cast_kernel(const float* __restrict__ x, float* __restrict__ y) {
    long i4 = blockIdx.x * (long)blockDim.x + threadIdx.x;
    float4 v = reinterpret_cast<const float4*>(x)[i4];
    float4 o;
    o.x = bf16v(v.x); o.y = bf16v(v.y); o.z = bf16v(v.z); o.w = bf16v(v.w);
    reinterpret_cast<float4*>(y)[i4] = o;
}

__global__ void dequant_kernel_f32(const int* __restrict__ codes,
                                   const float* __restrict__ absmax,
                                   float* __restrict__ w) {
    long i4 = blockIdx.x * (long)blockDim.x + threadIdx.x;
    int4 c = reinterpret_cast<const int4*>(codes)[i4];
    float am = __ldg(&absmax[(i4 * 4) >> 6]);
    float4 o;
    o.x = bf16v(FP4_TAB[c.x & 15] * am);
    o.y = bf16v(FP4_TAB[c.y & 15] * am);
    o.z = bf16v(FP4_TAB[c.z & 15] * am);
    o.w = bf16v(FP4_TAB[c.w & 15] * am);
    reinterpret_cast<float4*>(w)[i4] = o;
}

__global__ void dequant_kernel_bf16(const int* __restrict__ codes,
                                    const float* __restrict__ absmax,
                                    __nv_bfloat16* __restrict__ w) {
    long i4 = blockIdx.x * (long)blockDim.x + threadIdx.x;
    int4 c = reinterpret_cast<const int4*>(codes)[i4];
    float am = __ldg(&absmax[(i4 * 4) >> 6]);
    __nv_bfloat162 p0 = __floats2bfloat162_rn(FP4_TAB[c.x & 15] * am, FP4_TAB[c.y & 15] * am);
    __nv_bfloat162 p1 = __floats2bfloat162_rn(FP4_TAB[c.z & 15] * am, FP4_TAB[c.w & 15] * am);
    reinterpret_cast<__nv_bfloat162*>(w)[i4 * 2 + 0] = p0;
    reinterpret_cast<__nv_bfloat162*>(w)[i4 * 2 + 1] = p1;
}

// ---------------------------------------------------------------------------
// Layer 1: order-exact SGEMM on the FFMA2 pipe (R8 core, bf16 output).
// Each output element is ONE sequential IEEE-FMA chain over ascending k —
// this layer's order noise cascades twice, so it must stay sequential.
// ---------------------------------------------------------------------------

__global__ void __launch_bounds__(256)
sgemm_f32x2_l1(const float* __restrict__ A,   // [M,K] f32 (bf16 values)
               const float* __restrict__ W,   // [N,K] f32 (bf16 values)
               const float* __restrict__ bias,
               __nv_bfloat16* __restrict__ C,
               int M, int N, int K) {
    constexpr int BM = 128, BN = 128, BK = 16, LW = 132;
    __shared__ __align__(16) float sA[BK][LW];
    __shared__ __align__(16) float sB[BK][LW];

    const int tid  = threadIdx.x;
    const int lane = tid & 31;
    const int warp = tid >> 5;
    const int wm = (warp & 1) * 64;
    const int wn = (warp >> 1) * 32;
    const int lr = lane >> 2;
    const int lc = lane & 3;
    const int m0 = blockIdx.y * BM;
    const int n0 = blockIdx.x * BN;

    const int sr = tid >> 1;
    const int sc = (tid & 1) * 8;

    const float* gA = A + (size_t)(m0 + sr) * K + sc;
    const float* gW = W + (size_t)(n0 + sr) * K + sc;

    uint64_t acc[8][4];
    const uint64_t z2 = pack2(0.f, 0.f);
#pragma unroll
    for (int i = 0; i < 8; i++)
#pragma unroll
        for (int j = 0; j < 4; j++) acc[i][j] = z2;

    float4 ra0 = *reinterpret_cast<const float4*>(gA);
    float4 ra1 = *reinterpret_cast<const float4*>(gA + 4);
    float4 rb0 = *reinterpret_cast<const float4*>(gW);
    float4 rb1 = *reinterpret_cast<const float4*>(gW + 4);

    const int KT = K / BK;
    for (int kt = 0; kt < KT; ++kt) {
        sA[sc + 0][sr] = ra0.x; sA[sc + 1][sr] = ra0.y;
        sA[sc + 2][sr] = ra0.z; sA[sc + 3][sr] = ra0.w;
        sA[sc + 4][sr] = ra1.x; sA[sc + 5][sr] = ra1.y;
        sA[sc + 6][sr] = ra1.z; sA[sc + 7][sr] = ra1.w;
        sB[sc + 0][sr] = rb0.x; sB[sc + 1][sr] = rb0.y;
        sB[sc + 2][sr] = rb0.z; sB[sc + 3][sr] = rb0.w;
        sB[sc + 4][sr] = rb1.x; sB[sc + 5][sr] = rb1.y;
        sB[sc + 6][sr] = rb1.z; sB[sc + 7][sr] = rb1.w;
        __syncthreads();

        if (kt + 1 < KT) {
            gA += BK; gW += BK;
            ra0 = *reinterpret_cast<const float4*>(gA);
            ra1 = *reinterpret_cast<const float4*>(gA + 4);
            rb0 = *reinterpret_cast<const float4*>(gW);
            rb1 = *reinterpret_cast<const float4*>(gW + 4);
        }

#pragma unroll
        for (int k = 0; k < BK; k++) {   // ascending k — preserves chain order
            float a[8];
            *reinterpret_cast<float4*>(a)     = *reinterpret_cast<const float4*>(&sA[k][wm + lr * 8]);
            *reinterpret_cast<float4*>(a + 4) = *reinterpret_cast<const float4*>(&sA[k][wm + lr * 8 + 4]);
            uint64_t bp[4];
            const uint64_t* bq = reinterpret_cast<const uint64_t*>(&sB[k][wn + lc * 8]);
            bp[0] = bq[0]; bp[1] = bq[1]; bp[2] = bq[2]; bp[3] = bq[3];
#pragma unroll
            for (int i = 0; i < 8; i++) {
                const uint64_t ad = pack2(a[i], a[i]);
#pragma unroll
                for (int j = 0; j < 4; j++)
                    fma2(acc[i][j], ad, bp[j]);
            }
        }
        __syncthreads();
    }

    float bb[8];
#pragma unroll
    for (int j = 0; j < 8; j++) bb[j] = bf16v(bias[n0 + wn + lc * 8 + j]);

#pragma unroll
    for (int i = 0; i < 8; i++) {
        const int row = m0 + wm + lr * 8 + i;
        __nv_bfloat16* cp = C + (size_t)row * N + n0 + wn + lc * 8;
#pragma unroll
        for (int j = 0; j < 4; j++) {
            float v0, v1;
            unpack2(v0, v1, acc[i][j]);
            v0 = fmaxf(bf16v(bf16v(v0) + bb[2 * j]), 0.f);
            v1 = fmaxf(bf16v(bf16v(v1) + bb[2 * j + 1]), 0.f);
            reinterpret_cast<__nv_bfloat162*>(cp)[j] = __floats2bfloat162_rn(v0, v1);
        }
    }
}

// ---------------------------------------------------------------------------
// Layers 2-3: HMMA bf16 GEMM (R4 core). Last-layer / one-cascade order noise
// is admissible per the calibrated cascade model.
// ---------------------------------------------------------------------------

template <bool RELU, bool OUT_F32>
__global__ void __launch_bounds__(256)
gemm_hmma(const __nv_bfloat16* __restrict__ A,
          const __nv_bfloat16* __restrict__ W,
          const float* __restrict__ bias,
          void* __restrict__ Cv,
          int M, int N, int K) {
    constexpr int BM = 128, BN = 128, BK = 32;
    constexpr int LDS = BK + 8;

    __shared__ __align__(16) __nv_bfloat16 sA[2][BM * LDS];
    __shared__ __align__(16) __nv_bfloat16 sB[2][BN * LDS];

    const int tid = threadIdx.x;
    const int lane = tid & 31;
    const int warp = tid >> 5;
    const int wm = (warp & 1) * 64;
    const int wn = (warp >> 1) * 32;
    const int m0 = blockIdx.y * BM;
    const int n0 = blockIdx.x * BN;

    const int gid = lane >> 2;
    const int tg  = lane & 3;
    const int kfr = tg * 2;

    const int r_ld = tid >> 2;
    const int c_ld = (tid & 3) * 8;

    float acc[4][4][4];
#pragma unroll
    for (int i = 0; i < 4; i++)
#pragma unroll
        for (int j = 0; j < 4; j++)
#pragma unroll
            for (int q = 0; q < 4; q++) acc[i][j][q] = 0.f;

    auto load_stage = [&](int s, int kt) {
        const int k0 = kt * BK;
        const __nv_bfloat16* gA = A + (size_t)(m0 + r_ld) * K + k0 + c_ld;
        const __nv_bfloat16* gB = W + (size_t)(n0 + r_ld) * K + k0 + c_ld;
        cp16(s2u(&sA[s][r_ld * LDS + c_ld]), gA);
        cp16(s2u(&sB[s][r_ld * LDS + c_ld]), gB);
        cp16(s2u(&sA[s][(r_ld + 64) * LDS + c_ld]), gA + (size_t)64 * K);
        cp16(s2u(&sB[s][(r_ld + 64) * LDS + c_ld]), gB + (size_t)64 * K);
        cp_commit();
    };

    auto compute_stage = [&](int s) {
        const __nv_bfloat16* pA = sA[s];
        const __nv_bfloat16* pB = sB[s];
#pragma unroll
        for (int ks = 0; ks < 2; ks++) {
            const int kk = ks * 16;
            uint32_t a[4][4], b[4][2];
#pragma unroll
            for (int mt = 0; mt < 4; mt++) {
                const int r = wm + mt * 16 + gid;
                a[mt][0] = lds32u(&pA[(r    ) * LDS + kk + kfr    ]);
                a[mt][1] = lds32u(&pA[(r + 8) * LDS + kk + kfr    ]);
                a[mt][2] = lds32u(&pA[(r    ) * LDS + kk + kfr + 8]);
                a[mt][3] = lds32u(&pA[(r + 8) * LDS + kk + kfr + 8]);
            }
#pragma unroll
            for (int nt = 0; nt < 4; nt++) {
                const int n = wn + nt * 8 + gid;
                b[nt][0] = lds32u(&pB[n * LDS + kk + kfr    ]);
                b[nt][1] = lds32u(&pB[n * LDS + kk + kfr + 8]);
            }
#pragma unroll
            for (int mt = 0; mt < 4; mt++)
#pragma unroll
                for (int nt = 0; nt < 4; nt++)
                    mma16816(acc[mt][nt], a[mt], b[nt]);
        }
    };

    const int KT = K / BK;
    load_stage(0, 0);
    for (int kt = 0; kt < KT; ++kt) {
        if (kt + 1 < KT) {
            load_stage((kt + 1) & 1, kt + 1);
            cp_wait<1>();
        } else {
            cp_wait<0>();
        }
        __syncthreads();
        compute_stage(kt & 1);
        __syncthreads();
    }

    // Epilogue — reference rounding: bf16(dot) + bf16(bias) -> bf16 (+relu).
    __nv_bfloat16* Cb = (__nv_bfloat16*)Cv;
    float* Cf = (float*)Cv;
#pragma unroll
    for (int mt = 0; mt < 4; mt++) {
        const int rr = m0 + wm + mt * 16 + gid;
#pragma unroll
        for (int nt = 0; nt < 4; nt++) {
            const int cc = n0 + wn + nt * 8 + tg * 2;
            const float b0 = bf16v(bias[cc]);
            const float b1 = bf16v(bias[cc + 1]);
            const float* cr = acc[mt][nt];

            float v0 = bf16v(bf16v(cr[0]) + b0);
            float v1 = bf16v(bf16v(cr[1]) + b1);
            float v2 = bf16v(bf16v(cr[2]) + b0);
            float v3 = bf16v(bf16v(cr[3]) + b1);
            if (RELU) {
                v0 = fmaxf(v0, 0.f); v1 = fmaxf(v1, 0.f);
                v2 = fmaxf(v2, 0.f); v3 = fmaxf(v3, 0.f);
            }
            if (OUT_F32) {
                *reinterpret_cast<float2*>(&Cf[(size_t)rr * N + cc]) = make_float2(v0, v1);
                *reinterpret_cast<float2*>(&Cf[(size_t)(rr + 8) * N + cc]) = make_float2(v2, v3);
            } else {
                *reinterpret_cast<__nv_bfloat162*>(&Cb[(size_t)rr * N + cc]) =
                    __floats2bfloat162_rn(v0, v1);
                *reinterpret_cast<__nv_bfloat162*>(&Cb[(size_t)(rr + 8) * N + cc]) =
                    __floats2bfloat162_rn(v2, v3);
            }
        }
    }
}

// ---------------------------------------------------------------------------

extern "C" void kernel_launch(void* const* d_in, const int* in_sizes, int n_in,
                              void* d_out, int out_size) {
    // Resolve inputs by element count (robust to metadata ordering).
    const float* x = nullptr;
    const int *codes1 = nullptr, *codes2 = nullptr, *codes3 = nullptr;
    const float *absmax1 = nullptr, *absmax2 = nullptr, *absmax3 = nullptr;
    const float *bias1 = nullptr, *bias2 = nullptr, *bias3 = nullptr;

    for (int i = 0; i < n_in; i++) {
        const long sz = in_sizes[i];
        const void* p = d_in[i];
        if (sz == B_ * I_) x = (const float*)p;
        else if (sz == H_ * H_) codes2 = (const int*)p;
        else if (sz == H_ * I_) { if (!codes1) codes1 = (const int*)p; else codes3 = (const int*)p; }
        else if (sz == (H_ * H_) / 64) absmax2 = (const float*)p;
        else if (sz == (H_ * I_) / 64) { if (!absmax1) absmax1 = (const float*)p; else absmax3 = (const float*)p; }
        else if (sz == H_) { if (!bias1) bias1 = (const float*)p; else bias2 = (const float*)p; }
        else if (sz == O_) bias3 = (const float*)p;
    }

    float *Xf, *W1;
    __nv_bfloat16 *H1b, *W2b, *H2b, *W3b;
    cudaGetSymbolAddress((void**)&Xf, g_Xf);
    cudaGetSymbolAddress((void**)&W1, g_W1f);
    cudaGetSymbolAddress((void**)&H1b, g_H1b);
    cudaGetSymbolAddress((void**)&W2b, g_W2b);
    cudaGetSymbolAddress((void**)&H2b, g_H2b);
    cudaGetSymbolAddress((void**)&W3b, g_W3b);

    // elementwise prep
    cast_kernel<<<(unsigned)((B_ * I_) / 4 / 256), 256>>>(x, Xf);
    dequant_kernel_f32<<<(unsigned)((H_ * I_) / 4 / 256), 256>>>(codes1, absmax1, W1);
    dequant_kernel_bf16<<<(unsigned)((H_ * H_) / 4 / 256), 256>>>(codes2, absmax2, W2b);
    dequant_kernel_bf16<<<(unsigned)((O_ * H_) / 4 / 256), 256>>>(codes3, absmax3, W3b);

    // layer 1: sequential-chain f32x2 (order noise cascades twice -> must stay), bf16 out
    sgemm_f32x2_l1<<<dim3(H_ / 128, B_ / 128), 256>>>(
        Xf, W1, bias1, H1b, (int)B_, (int)H_, (int)I_);
    // layer 2: HMMA bf16 (+relu), bf16 out — one-cascade order noise ~3-5e-4, admissible
    gemm_hmma<true, false><<<dim3(H_ / 128, B_ / 128), 256>>>(
        H1b, W2b, bias2, H2b, (int)B_, (int)H_, (int)H_);
    // layer 3: HMMA bf16, f32 out (= upcast bf16)
    gemm_hmma<false, true><<<dim3(O_ / 128, B_ / 128), 256>>>(
        H2b, W3b, bias3, d_out, (int)B_, (int)O_, (int)H_);
}